// round 2
// baseline (speedup 1.0000x reference)
#include <cuda_runtime.h>

#define NPTS (96*96*96)   // 884736
#define HID 64
#define TPB 128
#define PPT 4             // points per thread = 2 packed pairs
#define NNEWT 36          // h in [0,NNEWT): FMA-Newton reciprocal; rest: MUFU rcp

typedef unsigned long long u64;

__device__ __forceinline__ u64 pk2(float lo, float hi) {
    u64 r; asm("mov.b64 %0,{%1,%2};" : "=l"(r) : "f"(lo), "f"(hi)); return r;
}
__device__ __forceinline__ void upk2(u64 v, float& lo, float& hi) {
    asm("mov.b64 {%0,%1},%2;" : "=f"(lo), "=f"(hi) : "l"(v));
}
__device__ __forceinline__ u64 fma2(u64 a, u64 b, u64 c) {
    u64 d; asm("fma.rn.f32x2 %0,%1,%2,%3;" : "=l"(d) : "l"(a), "l"(b), "l"(c)); return d;
}
__device__ __forceinline__ u64 mul2(u64 a, u64 b) {
    u64 d; asm("mul.rn.f32x2 %0,%1,%2;" : "=l"(d) : "l"(a), "l"(b)); return d;
}
__device__ __forceinline__ float ex2f(float x) {
    float r; asm("ex2.approx.f32 %0,%1;" : "=f"(r) : "f"(x)); return r;
}
__device__ __forceinline__ float rcpf(float x) {
    float r; asm("rcp.approx.f32 %0,%1;" : "=f"(r) : "f"(x)); return r;
}

// shared arrays per ode: 0..2 = W1 rows (prescaled, duplicated), 3 = b1 (prescaled, dup),
// 4..6 = +2*W2 cols (dup, Newton path), 7..9 = -2*W2 cols (dup, rcp path)
__global__ void __launch_bounds__(TPB)
diffeo_kernel(const float* __restrict__ coords,
              const float* __restrict__ W1_0, const float* __restrict__ b1_0,
              const float* __restrict__ W2_0, const float* __restrict__ b2_0,
              const float* __restrict__ W1_1, const float* __restrict__ b1_1,
              const float* __restrict__ W2_1, const float* __restrict__ b2_1,
              const float* __restrict__ img,
              float* __restrict__ out)
{
    __shared__ float2 sw[2][10][HID];
    __shared__ float  sS[2][3];

    const int tid = threadIdx.x;
    const float CEX = 2.8853900817779268f;  // 2*log2(e)

    if (tid < 6) {  // S_j = b2_j + sum_h W2[h][j]
        int ode = tid / 3, j = tid % 3;
        const float* W2 = ode ? W2_1 : W2_0;
        const float* b2 = ode ? b2_1 : b2_0;
        float s = b2[j];
        #pragma unroll 8
        for (int h = 0; h < HID; ++h) s += W2[h * 3 + j];
        sS[ode][j] = s;
    }
    if (tid < HID) {
        const int h = tid;
        #pragma unroll
        for (int ode = 0; ode < 2; ++ode) {
            const float* W1 = ode ? W1_1 : W1_0;
            const float* b1 = ode ? b1_1 : b1_0;
            const float* W2 = ode ? W2_1 : W2_0;
            float a0 = W1[h] * CEX, a1 = W1[HID + h] * CEX, a2 = W1[2 * HID + h] * CEX;
            float ab = b1[h] * CEX;
            sw[ode][0][h] = make_float2(a0, a0);
            sw[ode][1][h] = make_float2(a1, a1);
            sw[ode][2][h] = make_float2(a2, a2);
            sw[ode][3][h] = make_float2(ab, ab);
            float v0 = W2[h * 3 + 0], v1 = W2[h * 3 + 1], v2 = W2[h * 3 + 2];
            sw[ode][4][h] = make_float2( 2.f * v0,  2.f * v0);
            sw[ode][5][h] = make_float2( 2.f * v1,  2.f * v1);
            sw[ode][6][h] = make_float2( 2.f * v2,  2.f * v2);
            sw[ode][7][h] = make_float2(-2.f * v0, -2.f * v0);
            sw[ode][8][h] = make_float2(-2.f * v1, -2.f * v1);
            sw[ode][9][h] = make_float2(-2.f * v2, -2.f * v2);
        }
    }
    __syncthreads();

    const int base = (blockIdx.x * TPB + tid) * PPT;

    // Load 4 points (12 contiguous floats); pack pairs (pt0,pt1), (pt2,pt3)
    u64 yx[2], yy[2], yz[2];
    {
        const float4* c4 = reinterpret_cast<const float4*>(coords + (size_t)base * 3);
        float4 q0 = c4[0], q1 = c4[1], q2 = c4[2];
        yx[0] = pk2(q0.x, q0.w);  yy[0] = pk2(q0.y, q1.x);  yz[0] = pk2(q0.z, q1.y);
        yx[1] = pk2(q1.z, q2.y);  yy[1] = pk2(q1.w, q2.z);  yz[1] = pk2(q2.x, q2.w);
    }

    const u64 TWO2  = pk2( 2.0f,  2.0f);
    const u64 NTWO2 = pk2(-2.0f, -2.0f);
    const float hstep = 0.05f;

    #pragma unroll 1
    for (int ode = 0; ode < 2; ++ode) {
        const u64* pw0 = reinterpret_cast<const u64*>(sw[ode][0]);
        const u64* pw1 = reinterpret_cast<const u64*>(sw[ode][1]);
        const u64* pw2 = reinterpret_cast<const u64*>(sw[ode][2]);
        const u64* pbb = reinterpret_cast<const u64*>(sw[ode][3]);
        const u64* pvp0 = reinterpret_cast<const u64*>(sw[ode][4]);
        const u64* pvp1 = reinterpret_cast<const u64*>(sw[ode][5]);
        const u64* pvp2 = reinterpret_cast<const u64*>(sw[ode][6]);
        const u64* pvn0 = reinterpret_cast<const u64*>(sw[ode][7]);
        const u64* pvn1 = reinterpret_cast<const u64*>(sw[ode][8]);
        const u64* pvn2 = reinterpret_cast<const u64*>(sw[ode][9]);
        const u64 S0d = pk2(sS[ode][0], sS[ode][0]);
        const u64 S1d = pk2(sS[ode][1], sS[ode][1]);
        const u64 S2d = pk2(sS[ode][2], sS[ode][2]);

        #pragma unroll 1
        for (int step = 0; step < 4; ++step) {
            u64 ax[2], ay[2], az[2], tx[2], ty[2], tz[2];
            #pragma unroll
            for (int q = 0; q < 2; ++q) {
                ax[q] = yx[q]; ay[q] = yy[q]; az[q] = yz[q];
                tx[q] = yx[q]; ty[q] = yy[q]; tz[q] = yz[q];
            }

            #pragma unroll 1
            for (int s = 0; s < 4; ++s) {
                u64 kx[2] = {S0d, S0d}, ky[2] = {S1d, S1d}, kz[2] = {S2d, S2d};

                // Newton-reciprocal path (no MUFU rcp): r = 1/(1+e), k += r*(-2W2)
                #pragma unroll 2
                for (int hh = 0; hh < NNEWT; ++hh) {
                    u64 w0 = pw0[hh], w1 = pw1[hh], w2 = pw2[hh], bb = pbb[hh];
                    u64 v0 = pvp0[hh], v1 = pvp1[hh], v2 = pvp2[hh];
                    #pragma unroll
                    for (int q = 0; q < 2; ++q) {
                        u64 u2 = fma2(tx[q], w0, fma2(ty[q], w1, fma2(tz[q], w2, bb)));
                        float ul, uh; upk2(u2, ul, uh);
                        float el = ex2f(ul), eh = ex2f(uh);
                        float dl = el + 1.0f, dh = eh + 1.0f;
                        float r0l = __int_as_float(0x7EF311C3 - __float_as_int(dl));
                        float r0h = __int_as_float(0x7EF311C3 - __float_as_int(dh));
                        u64 d2 = pk2(dl, dh), r02 = pk2(r0l, r0h);
                        u64 t1 = fma2(d2, r02, NTWO2);   // d*r0 - 2
                        u64 m1 = mul2(r02, t1);          // = -r1
                        u64 t2 = fma2(d2, m1, TWO2);     // 2 - d*r1
                        u64 m2 = mul2(m1, t2);           // = -r2  (r = -m2)
                        // contribution r*(-2W2) == m2*(+2W2)
                        kx[q] = fma2(m2, v0, kx[q]);
                        ky[q] = fma2(m2, v1, ky[q]);
                        kz[q] = fma2(m2, v2, kz[q]);
                    }
                }
                // MUFU rcp path
                #pragma unroll 2
                for (int hh = NNEWT; hh < HID; ++hh) {
                    u64 w0 = pw0[hh], w1 = pw1[hh], w2 = pw2[hh], bb = pbb[hh];
                    u64 v0 = pvn0[hh], v1 = pvn1[hh], v2 = pvn2[hh];
                    #pragma unroll
                    for (int q = 0; q < 2; ++q) {
                        u64 u2 = fma2(tx[q], w0, fma2(ty[q], w1, fma2(tz[q], w2, bb)));
                        float ul, uh; upk2(u2, ul, uh);
                        float el = ex2f(ul), eh = ex2f(uh);
                        float rl = rcpf(el + 1.0f), rh = rcpf(eh + 1.0f);
                        u64 r2 = pk2(rl, rh);
                        kx[q] = fma2(r2, v0, kx[q]);
                        ky[q] = fma2(r2, v1, ky[q]);
                        kz[q] = fma2(r2, v2, kz[q]);
                    }
                }

                float wa = (s == 0 || s == 3) ? (hstep * (1.0f / 6.0f)) : (hstep * (1.0f / 3.0f));
                float wn = (s < 2) ? (0.5f * hstep) : ((s == 2) ? hstep : 0.0f);
                u64 wa2 = pk2(wa, wa), wn2 = pk2(wn, wn);
                #pragma unroll
                for (int q = 0; q < 2; ++q) {
                    ax[q] = fma2(wa2, kx[q], ax[q]);
                    ay[q] = fma2(wa2, ky[q], ay[q]);
                    az[q] = fma2(wa2, kz[q], az[q]);
                    tx[q] = fma2(wn2, kx[q], yx[q]);
                    ty[q] = fma2(wn2, ky[q], yy[q]);
                    tz[q] = fma2(wn2, kz[q], yz[q]);
                }
            }
            #pragma unroll
            for (int q = 0; q < 2; ++q) { yx[q] = ax[q]; yy[q] = ay[q]; yz[q] = az[q]; }
        }
    }

    // Unpack final coords
    float fy[PPT][3];
    upk2(yx[0], fy[0][0], fy[1][0]); upk2(yy[0], fy[0][1], fy[1][1]); upk2(yz[0], fy[0][2], fy[1][2]);
    upk2(yx[1], fy[2][0], fy[3][0]); upk2(yy[1], fy[2][1], fy[3][1]); upk2(yz[1], fy[2][2], fy[3][2]);

    // Trilinear grid sample of img (128^3), zeros padding, align_corners=False
    #pragma unroll
    for (int p = 0; p < PPT; ++p) {
        float xx = fmaf(fy[p][2], 64.0f, 63.5f);
        float yyc = fmaf(fy[p][1], 64.0f, 63.5f);
        float zz = fmaf(fy[p][0], 64.0f, 63.5f);
        float xf = floorf(xx), yf = floorf(yyc), zf = floorf(zz);
        float txw = xx - xf, tyw = yyc - yf, tzw = zz - zf;
        int x0 = (int)xf, y0i = (int)yf, z0 = (int)zf;

        float sacc = 0.0f;
        #pragma unroll
        for (int dz = 0; dz < 2; ++dz) {
            float wz = dz ? tzw : (1.0f - tzw);
            int zi = z0 + dz;
            #pragma unroll
            for (int dy = 0; dy < 2; ++dy) {
                float wy = dy ? tyw : (1.0f - tyw);
                int yi = y0i + dy;
                #pragma unroll
                for (int dx = 0; dx < 2; ++dx) {
                    float wx = dx ? txw : (1.0f - txw);
                    int xi = x0 + dx;
                    if ((unsigned)xi < 128u && (unsigned)yi < 128u && (unsigned)zi < 128u) {
                        float v = __ldg(&img[((size_t)zi * 128 + yi) * 128 + xi]);
                        sacc = fmaf(v, wz * wy * wx, sacc);
                    }
                }
            }
        }
        out[base + p] = (sacc - 0.5f) * 2.0f;
    }

    // Write c1 after reg_out
    {
        float* outc = out + NPTS;
        float4* o4 = reinterpret_cast<float4*>(outc + (size_t)base * 3);
        o4[0] = make_float4(fy[0][0], fy[0][1], fy[0][2], fy[1][0]);
        o4[1] = make_float4(fy[1][1], fy[1][2], fy[2][0], fy[2][1]);
        o4[2] = make_float4(fy[2][2], fy[3][0], fy[3][1], fy[3][2]);
    }
}

extern "C" void kernel_launch(void* const* d_in, const int* in_sizes, int n_in,
                              void* d_out, int out_size)
{
    const float* coords = (const float*)d_in[0];
    const float* W1_0   = (const float*)d_in[1];
    const float* b1_0   = (const float*)d_in[2];
    const float* W2_0   = (const float*)d_in[3];
    const float* b2_0   = (const float*)d_in[4];
    const float* W1_1   = (const float*)d_in[5];
    const float* b1_1   = (const float*)d_in[6];
    const float* W2_1   = (const float*)d_in[7];
    const float* b2_1   = (const float*)d_in[8];
    const float* img    = (const float*)d_in[9];
    float* out = (float*)d_out;

    const int nblocks = NPTS / (TPB * PPT);  // 1728
    diffeo_kernel<<<nblocks, TPB>>>(coords,
                                    W1_0, b1_0, W2_0, b2_0,
                                    W1_1, b1_1, W2_1, b2_1,
                                    img, out);
}

// round 3
// speedup vs baseline: 1.0449x; 1.0449x over previous
#include <cuda_runtime.h>

#define NPTS (96*96*96)   // 884736
#define HID 64
#define TPB 128
#define PPT 8             // points per thread = 4 packed pairs
#define NQ  4

typedef unsigned long long u64;

__device__ __forceinline__ u64 pk2(float lo, float hi) {
    u64 r; asm("mov.b64 %0,{%1,%2};" : "=l"(r) : "f"(lo), "f"(hi)); return r;
}
__device__ __forceinline__ void upk2(u64 v, float& lo, float& hi) {
    asm("mov.b64 {%0,%1},%2;" : "=f"(lo), "=f"(hi) : "l"(v));
}
__device__ __forceinline__ u64 fma2(u64 a, u64 b, u64 c) {
    u64 d; asm("fma.rn.f32x2 %0,%1,%2,%3;" : "=l"(d) : "l"(a), "l"(b), "l"(c)); return d;
}
__device__ __forceinline__ float ex2f(float x) {
    float r; asm("ex2.approx.f32 %0,%1;" : "=f"(r) : "f"(x)); return r;
}
__device__ __forceinline__ float rcpf(float x) {
    float r; asm("rcp.approx.f32 %0,%1;" : "=f"(r) : "f"(x)); return r;
}

// Per-h weight record: 4 x ulonglong2 = 64B
//   [0] = {w0d, w1d}   W1 rows, prescaled by 2*log2(e), duplicated
//   [1] = {w2d, bbd}   third W1 row + prescaled b1
//   [2] = {v0d, v1d}   -2*W2 cols, duplicated
//   [3] = {v2d, pad}
__global__ void __launch_bounds__(TPB)
diffeo_kernel(const float* __restrict__ coords,
              const float* __restrict__ W1_0, const float* __restrict__ b1_0,
              const float* __restrict__ W2_0, const float* __restrict__ b2_0,
              const float* __restrict__ W1_1, const float* __restrict__ b1_1,
              const float* __restrict__ W2_1, const float* __restrict__ b2_1,
              const float* __restrict__ img,
              float* __restrict__ out)
{
    __shared__ ulonglong2 swp[2][HID][4];
    __shared__ float sS[2][3];

    const int tid = threadIdx.x;
    const float CEX = 2.8853900817779268f;  // 2*log2(e)

    if (tid < 6) {  // S_j = b2_j + sum_h W2[h][j]
        int ode = tid / 3, j = tid % 3;
        const float* W2 = ode ? W2_1 : W2_0;
        const float* b2 = ode ? b2_1 : b2_0;
        float s = b2[j];
        #pragma unroll 8
        for (int h = 0; h < HID; ++h) s += W2[h * 3 + j];
        sS[ode][j] = s;
    }
    if (tid < HID) {
        const int h = tid;
        #pragma unroll
        for (int ode = 0; ode < 2; ++ode) {
            const float* W1 = ode ? W1_1 : W1_0;
            const float* b1 = ode ? b1_1 : b1_0;
            const float* W2 = ode ? W2_1 : W2_0;
            float a0 = W1[h] * CEX, a1 = W1[HID + h] * CEX, a2 = W1[2 * HID + h] * CEX;
            float ab = b1[h] * CEX;
            float v0 = -2.f * W2[h * 3 + 0];
            float v1 = -2.f * W2[h * 3 + 1];
            float v2 = -2.f * W2[h * 3 + 2];
            swp[ode][h][0] = make_ulonglong2(pk2(a0, a0), pk2(a1, a1));
            swp[ode][h][1] = make_ulonglong2(pk2(a2, a2), pk2(ab, ab));
            swp[ode][h][2] = make_ulonglong2(pk2(v0, v0), pk2(v1, v1));
            swp[ode][h][3] = make_ulonglong2(pk2(v2, v2), 0ull);
        }
    }
    __syncthreads();

    const int base = (blockIdx.x * TPB + tid) * PPT;

    // Load 8 points (24 contiguous floats) as 6x float4; pack pairs
    u64 yx[NQ], yy[NQ], yz[NQ];
    {
        const float4* c4 = reinterpret_cast<const float4*>(coords + (size_t)base * 3);
        float4 q0 = c4[0], q1 = c4[1], q2 = c4[2], q3 = c4[3], q4 = c4[4], q5 = c4[5];
        yx[0] = pk2(q0.x, q0.w);  yy[0] = pk2(q0.y, q1.x);  yz[0] = pk2(q0.z, q1.y);
        yx[1] = pk2(q1.z, q2.y);  yy[1] = pk2(q1.w, q2.z);  yz[1] = pk2(q2.x, q2.w);
        yx[2] = pk2(q3.x, q3.w);  yy[2] = pk2(q3.y, q4.x);  yz[2] = pk2(q3.z, q4.y);
        yx[3] = pk2(q4.z, q5.y);  yy[3] = pk2(q4.w, q5.z);  yz[3] = pk2(q5.x, q5.w);
    }

    const float hstep = 0.05f;

    #pragma unroll 1
    for (int ode = 0; ode < 2; ++ode) {
        const ulonglong2* pw = &swp[ode][0][0];
        const u64 S0d = pk2(sS[ode][0], sS[ode][0]);
        const u64 S1d = pk2(sS[ode][1], sS[ode][1]);
        const u64 S2d = pk2(sS[ode][2], sS[ode][2]);

        #pragma unroll 1
        for (int step = 0; step < 4; ++step) {
            u64 ax[NQ], ay[NQ], az[NQ], tx[NQ], ty[NQ], tz[NQ];
            #pragma unroll
            for (int q = 0; q < NQ; ++q) {
                ax[q] = yx[q]; ay[q] = yy[q]; az[q] = yz[q];
                tx[q] = yx[q]; ty[q] = yy[q]; tz[q] = yz[q];
            }

            #pragma unroll 1
            for (int s = 0; s < 4; ++s) {
                u64 kx[NQ], ky[NQ], kz[NQ];
                #pragma unroll
                for (int q = 0; q < NQ; ++q) { kx[q] = S0d; ky[q] = S1d; kz[q] = S2d; }

                #pragma unroll 2
                for (int hh = 0; hh < HID; ++hh) {
                    ulonglong2 g0 = pw[hh * 4 + 0];
                    ulonglong2 g1 = pw[hh * 4 + 1];
                    ulonglong2 g2 = pw[hh * 4 + 2];
                    u64 v2d = reinterpret_cast<const u64*>(pw + hh * 4 + 3)[0];
                    u64 w0 = g0.x, w1 = g0.y, w2 = g1.x, bb = g1.y;
                    u64 v0 = g2.x, v1 = g2.y;
                    #pragma unroll
                    for (int q = 0; q < NQ; ++q) {
                        u64 u2 = fma2(tx[q], w0, fma2(ty[q], w1, fma2(tz[q], w2, bb)));
                        float ul, uh; upk2(u2, ul, uh);
                        float el = ex2f(ul), eh = ex2f(uh);
                        float rl = rcpf(el + 1.0f);
                        float rh = rcpf(eh + 1.0f);
                        u64 r2 = pk2(rl, rh);
                        kx[q] = fma2(r2, v0, kx[q]);
                        ky[q] = fma2(r2, v1, ky[q]);
                        kz[q] = fma2(r2, v2d, kz[q]);
                    }
                }

                float wa = (s == 0 || s == 3) ? (hstep * (1.0f / 6.0f)) : (hstep * (1.0f / 3.0f));
                float wn = (s < 2) ? (0.5f * hstep) : ((s == 2) ? hstep : 0.0f);
                u64 wa2 = pk2(wa, wa), wn2 = pk2(wn, wn);
                #pragma unroll
                for (int q = 0; q < NQ; ++q) {
                    ax[q] = fma2(wa2, kx[q], ax[q]);
                    ay[q] = fma2(wa2, ky[q], ay[q]);
                    az[q] = fma2(wa2, kz[q], az[q]);
                    tx[q] = fma2(wn2, kx[q], yx[q]);
                    ty[q] = fma2(wn2, ky[q], yy[q]);
                    tz[q] = fma2(wn2, kz[q], yz[q]);
                }
            }
            #pragma unroll
            for (int q = 0; q < NQ; ++q) { yx[q] = ax[q]; yy[q] = ay[q]; yz[q] = az[q]; }
        }
    }

    // Unpack final coords
    float fy[PPT][3];
    #pragma unroll
    for (int q = 0; q < NQ; ++q) {
        upk2(yx[q], fy[2*q][0], fy[2*q+1][0]);
        upk2(yy[q], fy[2*q][1], fy[2*q+1][1]);
        upk2(yz[q], fy[2*q][2], fy[2*q+1][2]);
    }

    // Trilinear grid sample of img (128^3), zeros padding, align_corners=False
    #pragma unroll
    for (int p = 0; p < PPT; ++p) {
        float xx = fmaf(fy[p][2], 64.0f, 63.5f);
        float yyc = fmaf(fy[p][1], 64.0f, 63.5f);
        float zz = fmaf(fy[p][0], 64.0f, 63.5f);
        float xf = floorf(xx), yf = floorf(yyc), zf = floorf(zz);
        float txw = xx - xf, tyw = yyc - yf, tzw = zz - zf;
        int x0 = (int)xf, y0i = (int)yf, z0 = (int)zf;

        float sacc = 0.0f;
        #pragma unroll
        for (int dz = 0; dz < 2; ++dz) {
            float wz = dz ? tzw : (1.0f - tzw);
            int zi = z0 + dz;
            #pragma unroll
            for (int dy = 0; dy < 2; ++dy) {
                float wy = dy ? tyw : (1.0f - tyw);
                int yi = y0i + dy;
                #pragma unroll
                for (int dx = 0; dx < 2; ++dx) {
                    float wx = dx ? txw : (1.0f - txw);
                    int xi = x0 + dx;
                    if ((unsigned)xi < 128u && (unsigned)yi < 128u && (unsigned)zi < 128u) {
                        float v = __ldg(&img[((size_t)zi * 128 + yi) * 128 + xi]);
                        sacc = fmaf(v, wz * wy * wx, sacc);
                    }
                }
            }
        }
        out[base + p] = (sacc - 0.5f) * 2.0f;
    }

    // Write c1 after reg_out, 24 floats as 6x float4
    {
        float* outc = out + NPTS;
        float4* o4 = reinterpret_cast<float4*>(outc + (size_t)base * 3);
        o4[0] = make_float4(fy[0][0], fy[0][1], fy[0][2], fy[1][0]);
        o4[1] = make_float4(fy[1][1], fy[1][2], fy[2][0], fy[2][1]);
        o4[2] = make_float4(fy[2][2], fy[3][0], fy[3][1], fy[3][2]);
        o4[3] = make_float4(fy[4][0], fy[4][1], fy[4][2], fy[5][0]);
        o4[4] = make_float4(fy[5][1], fy[5][2], fy[6][0], fy[6][1]);
        o4[5] = make_float4(fy[6][2], fy[7][0], fy[7][1], fy[7][2]);
    }
}

extern "C" void kernel_launch(void* const* d_in, const int* in_sizes, int n_in,
                              void* d_out, int out_size)
{
    const float* coords = (const float*)d_in[0];
    const float* W1_0   = (const float*)d_in[1];
    const float* b1_0   = (const float*)d_in[2];
    const float* W2_0   = (const float*)d_in[3];
    const float* b2_0   = (const float*)d_in[4];
    const float* W1_1   = (const float*)d_in[5];
    const float* b1_1   = (const float*)d_in[6];
    const float* W2_1   = (const float*)d_in[7];
    const float* b2_1   = (const float*)d_in[8];
    const float* img    = (const float*)d_in[9];
    float* out = (float*)d_out;

    const int nblocks = NPTS / (TPB * PPT);  // 864
    diffeo_kernel<<<nblocks, TPB>>>(coords,
                                    W1_0, b1_0, W2_0, b2_0,
                                    W1_1, b1_1, W2_1, b2_1,
                                    img, out);
}

// round 4
// speedup vs baseline: 1.0548x; 1.0095x over previous
#include <cuda_runtime.h>

#define NPTS (96*96*96)   // 884736
#define HID 64
#define TPB 256
#define PPT 4             // points per thread = 2 packed pairs
#define NQ  2
#define NNEWT 48          // h in [0,NNEWT): FMA-Newton reciprocal; rest: MUFU rcp

typedef unsigned long long u64;

__device__ __forceinline__ u64 pk2(float lo, float hi) {
    u64 r; asm("mov.b64 %0,{%1,%2};" : "=l"(r) : "f"(lo), "f"(hi)); return r;
}
__device__ __forceinline__ void upk2(u64 v, float& lo, float& hi) {
    asm("mov.b64 {%0,%1},%2;" : "=f"(lo), "=f"(hi) : "l"(v));
}
__device__ __forceinline__ u64 fma2(u64 a, u64 b, u64 c) {
    u64 d; asm("fma.rn.f32x2 %0,%1,%2,%3;" : "=l"(d) : "l"(a), "l"(b), "l"(c)); return d;
}
__device__ __forceinline__ u64 mul2(u64 a, u64 b) {
    u64 d; asm("mul.rn.f32x2 %0,%1,%2;" : "=l"(d) : "l"(a), "l"(b)); return d;
}
__device__ __forceinline__ u64 add2(u64 a, u64 b) {
    u64 d; asm("add.rn.f32x2 %0,%1,%2;" : "=l"(d) : "l"(a), "l"(b)); return d;
}
__device__ __forceinline__ float ex2f(float x) {
    float r; asm("ex2.approx.f32 %0,%1;" : "=f"(r) : "f"(x)); return r;
}
__device__ __forceinline__ float rcpf(float x) {
    float r; asm("rcp.approx.f32 %0,%1;" : "=f"(r) : "f"(x)); return r;
}

// Per-h weight record (4 x ulonglong2 = 64B):
//  A={w0d,w1d} B={w2d,bbd}  (W1 rows & b1, prescaled by 2*log2e, duplicated)
//  C={v0d,v1d} D={v2d,pad}  (h<NNEWT: +2*W2 dup; h>=NNEWT: -2*W2 dup)
__global__ void __launch_bounds__(TPB)
diffeo_kernel(const float* __restrict__ coords,
              const float* __restrict__ W1_0, const float* __restrict__ b1_0,
              const float* __restrict__ W2_0, const float* __restrict__ b2_0,
              const float* __restrict__ W1_1, const float* __restrict__ b1_1,
              const float* __restrict__ W2_1, const float* __restrict__ b2_1,
              const float* __restrict__ img,
              float* __restrict__ out)
{
    __shared__ ulonglong2 swp[2][HID][4];
    __shared__ float sS[2][3];

    const int tid = threadIdx.x;
    const float CEX = 2.8853900817779268f;  // 2*log2(e)

    if (tid < 6) {  // S_j = b2_j + sum_h W2[h][j]   (from t = 1 - 2r fold)
        int ode = tid / 3, j = tid % 3;
        const float* W2 = ode ? W2_1 : W2_0;
        const float* b2 = ode ? b2_1 : b2_0;
        float s = b2[j];
        #pragma unroll 8
        for (int h = 0; h < HID; ++h) s += W2[h * 3 + j];
        sS[ode][j] = s;
    }
    if (tid < HID) {
        const int h = tid;
        const float vsgn = (h < NNEWT) ? 2.0f : -2.0f;
        #pragma unroll
        for (int ode = 0; ode < 2; ++ode) {
            const float* W1 = ode ? W1_1 : W1_0;
            const float* b1 = ode ? b1_1 : b1_0;
            const float* W2 = ode ? W2_1 : W2_0;
            float a0 = W1[h] * CEX, a1 = W1[HID + h] * CEX, a2 = W1[2 * HID + h] * CEX;
            float ab = b1[h] * CEX;
            float v0 = vsgn * W2[h * 3 + 0];
            float v1 = vsgn * W2[h * 3 + 1];
            float v2 = vsgn * W2[h * 3 + 2];
            swp[ode][h][0] = make_ulonglong2(pk2(a0, a0), pk2(a1, a1));
            swp[ode][h][1] = make_ulonglong2(pk2(a2, a2), pk2(ab, ab));
            swp[ode][h][2] = make_ulonglong2(pk2(v0, v0), pk2(v1, v1));
            swp[ode][h][3] = make_ulonglong2(pk2(v2, v2), 0ull);
        }
    }
    __syncthreads();

    const int base = (blockIdx.x * TPB + tid) * PPT;

    // Load 4 points (12 floats) as 3x float4; pack pairs (pt0,pt1),(pt2,pt3)
    u64 yx[NQ], yy[NQ], yz[NQ];
    {
        const float4* c4 = reinterpret_cast<const float4*>(coords + (size_t)base * 3);
        float4 q0 = c4[0], q1 = c4[1], q2 = c4[2];
        yx[0] = pk2(q0.x, q0.w);  yy[0] = pk2(q0.y, q1.x);  yz[0] = pk2(q0.z, q1.y);
        yx[1] = pk2(q1.z, q2.y);  yy[1] = pk2(q1.w, q2.z);  yz[1] = pk2(q2.x, q2.w);
    }

    const u64 ONE2  = pk2(1.0f, 1.0f);
    const u64 TWO2  = pk2(2.0f, 2.0f);
    const u64 NTWO2 = pk2(-2.0f, -2.0f);
    const float hstep = 0.05f;

    #pragma unroll 1
    for (int ode = 0; ode < 2; ++ode) {
        const ulonglong2* pw = &swp[ode][0][0];
        const u64 S0d = pk2(sS[ode][0], sS[ode][0]);
        const u64 S1d = pk2(sS[ode][1], sS[ode][1]);
        const u64 S2d = pk2(sS[ode][2], sS[ode][2]);

        #pragma unroll 1
        for (int step = 0; step < 4; ++step) {
            u64 ax[NQ], ay[NQ], az[NQ], tx[NQ], ty[NQ], tz[NQ];
            #pragma unroll
            for (int q = 0; q < NQ; ++q) {
                ax[q] = yx[q]; ay[q] = yy[q]; az[q] = yz[q];
                tx[q] = yx[q]; ty[q] = yy[q]; tz[q] = yz[q];
            }

            #pragma unroll 1
            for (int s = 0; s < 4; ++s) {
                u64 kx[NQ], ky[NQ], kz[NQ];
                #pragma unroll
                for (int q = 0; q < NQ; ++q) { kx[q] = S0d; ky[q] = S1d; kz[q] = S2d; }

                // ---- Newton path: r = 1/(1+2^v), bit-trick init + 2 packed iters
                #pragma unroll 2
                for (int hh = 0; hh < NNEWT; ++hh) {
                    ulonglong2 g0 = pw[hh * 4 + 0];
                    ulonglong2 g1 = pw[hh * 4 + 1];
                    ulonglong2 g2 = pw[hh * 4 + 2];
                    u64 v2d = reinterpret_cast<const u64*>(pw + hh * 4 + 3)[0];
                    #pragma unroll
                    for (int q = 0; q < NQ; ++q) {
                        u64 u2 = fma2(tx[q], g0.x, fma2(ty[q], g0.y, fma2(tz[q], g1.x, g1.y)));
                        float ul, uh; upk2(u2, ul, uh);
                        float el = ex2f(ul), eh = ex2f(uh);
                        u64 d2 = add2(pk2(el, eh), ONE2);
                        float dl, dh; upk2(d2, dl, dh);
                        float r0l = __int_as_float(0x7EF311C3 - __float_as_int(dl));
                        float r0h = __int_as_float(0x7EF311C3 - __float_as_int(dh));
                        u64 r02 = pk2(r0l, r0h);
                        u64 t1 = fma2(d2, r02, NTWO2);   // d*r0 - 2
                        u64 m1 = mul2(r02, t1);          // -r1
                        u64 t2 = fma2(d2, m1, TWO2);     // 2 - d*r1
                        u64 m2 = mul2(m1, t2);           // -r2   (r = -m2)
                        // r*(-2W2) == m2*(+2W2); C,D hold +2W2 here
                        kx[q] = fma2(m2, g2.x, kx[q]);
                        ky[q] = fma2(m2, g2.y, ky[q]);
                        kz[q] = fma2(m2, v2d, kz[q]);
                    }
                }
                // ---- MUFU rcp path (C,D hold -2W2)
                #pragma unroll 2
                for (int hh = NNEWT; hh < HID; ++hh) {
                    ulonglong2 g0 = pw[hh * 4 + 0];
                    ulonglong2 g1 = pw[hh * 4 + 1];
                    ulonglong2 g2 = pw[hh * 4 + 2];
                    u64 v2d = reinterpret_cast<const u64*>(pw + hh * 4 + 3)[0];
                    #pragma unroll
                    for (int q = 0; q < NQ; ++q) {
                        u64 u2 = fma2(tx[q], g0.x, fma2(ty[q], g0.y, fma2(tz[q], g1.x, g1.y)));
                        float ul, uh; upk2(u2, ul, uh);
                        float el = ex2f(ul), eh = ex2f(uh);
                        u64 d2 = add2(pk2(el, eh), ONE2);
                        float dl, dh; upk2(d2, dl, dh);
                        u64 r2 = pk2(rcpf(dl), rcpf(dh));
                        kx[q] = fma2(r2, g2.x, kx[q]);
                        ky[q] = fma2(r2, g2.y, ky[q]);
                        kz[q] = fma2(r2, v2d, kz[q]);
                    }
                }

                float wa = (s == 0 || s == 3) ? (hstep * (1.0f / 6.0f)) : (hstep * (1.0f / 3.0f));
                float wn = (s < 2) ? (0.5f * hstep) : ((s == 2) ? hstep : 0.0f);
                u64 wa2 = pk2(wa, wa), wn2 = pk2(wn, wn);
                #pragma unroll
                for (int q = 0; q < NQ; ++q) {
                    ax[q] = fma2(wa2, kx[q], ax[q]);
                    ay[q] = fma2(wa2, ky[q], ay[q]);
                    az[q] = fma2(wa2, kz[q], az[q]);
                    tx[q] = fma2(wn2, kx[q], yx[q]);
                    ty[q] = fma2(wn2, ky[q], yy[q]);
                    tz[q] = fma2(wn2, kz[q], yz[q]);
                }
            }
            #pragma unroll
            for (int q = 0; q < NQ; ++q) { yx[q] = ax[q]; yy[q] = ay[q]; yz[q] = az[q]; }
        }
    }

    // Unpack final coords
    float fy[PPT][3];
    #pragma unroll
    for (int q = 0; q < NQ; ++q) {
        upk2(yx[q], fy[2*q][0], fy[2*q+1][0]);
        upk2(yy[q], fy[2*q][1], fy[2*q+1][1]);
        upk2(yz[q], fy[2*q][2], fy[2*q+1][2]);
    }

    // Trilinear grid sample of img (128^3), zeros padding, align_corners=False
    #pragma unroll
    for (int p = 0; p < PPT; ++p) {
        float xx = fmaf(fy[p][2], 64.0f, 63.5f);
        float yyc = fmaf(fy[p][1], 64.0f, 63.5f);
        float zz = fmaf(fy[p][0], 64.0f, 63.5f);
        float xf = floorf(xx), yf = floorf(yyc), zf = floorf(zz);
        float txw = xx - xf, tyw = yyc - yf, tzw = zz - zf;
        int x0 = (int)xf, y0i = (int)yf, z0 = (int)zf;

        float sacc = 0.0f;
        #pragma unroll
        for (int dz = 0; dz < 2; ++dz) {
            float wz = dz ? tzw : (1.0f - tzw);
            int zi = z0 + dz;
            #pragma unroll
            for (int dy = 0; dy < 2; ++dy) {
                float wy = dy ? tyw : (1.0f - tyw);
                int yi = y0i + dy;
                #pragma unroll
                for (int dx = 0; dx < 2; ++dx) {
                    float wx = dx ? txw : (1.0f - txw);
                    int xi = x0 + dx;
                    if ((unsigned)xi < 128u && (unsigned)yi < 128u && (unsigned)zi < 128u) {
                        float v = __ldg(&img[((size_t)zi * 128 + yi) * 128 + xi]);
                        sacc = fmaf(v, wz * wy * wx, sacc);
                    }
                }
            }
        }
        out[base + p] = (sacc - 0.5f) * 2.0f;
    }

    // Write c1 after reg_out, 12 floats as 3x float4
    {
        float* outc = out + NPTS;
        float4* o4 = reinterpret_cast<float4*>(outc + (size_t)base * 3);
        o4[0] = make_float4(fy[0][0], fy[0][1], fy[0][2], fy[1][0]);
        o4[1] = make_float4(fy[1][1], fy[1][2], fy[2][0], fy[2][1]);
        o4[2] = make_float4(fy[2][2], fy[3][0], fy[3][1], fy[3][2]);
    }
}

extern "C" void kernel_launch(void* const* d_in, const int* in_sizes, int n_in,
                              void* d_out, int out_size)
{
    const float* coords = (const float*)d_in[0];
    const float* W1_0   = (const float*)d_in[1];
    const float* b1_0   = (const float*)d_in[2];
    const float* W2_0   = (const float*)d_in[3];
    const float* b2_0   = (const float*)d_in[4];
    const float* W1_1   = (const float*)d_in[5];
    const float* b1_1   = (const float*)d_in[6];
    const float* W2_1   = (const float*)d_in[7];
    const float* b2_1   = (const float*)d_in[8];
    const float* img    = (const float*)d_in[9];
    float* out = (float*)d_out;

    const int nblocks = NPTS / (TPB * PPT);  // 864
    diffeo_kernel<<<nblocks, TPB>>>(coords,
                                    W1_0, b1_0, W2_0, b2_0,
                                    W1_1, b1_1, W2_1, b2_1,
                                    img, out);
}